// round 2
// baseline (speedup 1.0000x reference)
#include <cuda_runtime.h>
#include <math.h>

#define BSZ 16
#define SEQ 2048
#define DKK 64
#define BQ 64
#define BK 64
#define NT 256
#define QS 68            // padded row stride for QsT/KsT/Ps (17*16B -> aligned float4, staggered banks)

// smem layout (floats):
//  QsT [64][68]  (d-major, transposed Q, pre-scaled by 1/8)
//  KsT [64][68]  (d-major, transposed K)
//  Vs  [64][64]  (j-major)
//  Rel [64][128] (d-major window of Krelpos columns)
//  Ps  [64][68]  (softmax probs, row-major)
#define SM_QST 0
#define SM_KST (SM_QST + 64*QS)
#define SM_VS  (SM_KST + 64*QS)
#define SM_REL (SM_VS  + 64*64)
#define SM_PS  (SM_REL + 64*128)
#define SM_FLOATS (SM_PS + 64*QS)
#define SMEM_BYTES (SM_FLOATS * 4)

__global__ __launch_bounds__(NT, 2)
void attn_relpos_kernel(const float* __restrict__ Q, const float* __restrict__ K,
                        const float* __restrict__ V, const float* __restrict__ R,
                        float* __restrict__ O)
{
    extern __shared__ float smem[];
    float* QsT = smem + SM_QST;
    float* KsT = smem + SM_KST;
    float* Vs  = smem + SM_VS;
    float* Rel = smem + SM_REL;
    float* Ps  = smem + SM_PS;

    const int tid = threadIdx.x;
    const int tx = tid & 15;      // col group (4 cols each)
    const int ty = tid >> 4;      // row group (4 rows each)

    // reversed tile order: heavy (long causal loop) CTAs launch first
    const int bq = (int)gridDim.x - 1 - (int)blockIdx.x;
    const int i0 = bq * BQ;
    const int b  = blockIdx.y;

    const float* Qb = Q + ((size_t)b * SEQ + i0) * DKK;

    // ---- load Q tile, transposed + pre-scaled by 1/sqrt(64) ----
    #pragma unroll
    for (int idx = tid; idx < BQ * DKK; idx += NT) {
        int i = idx >> 6, d = idx & 63;
        QsT[d * QS + i] = Qb[idx] * 0.125f;
    }

    float accO[16];
    #pragma unroll
    for (int x = 0; x < 16; ++x) accO[x] = 0.f;
    float m_i[4], l_i[4];
    #pragma unroll
    for (int x = 0; x < 4; ++x) { m_i[x] = -INFINITY; l_i[x] = 0.f; }

    const int relbase = 63 + 4 * (tx - ty);   // in [3,123]; relbase-3 is 16B aligned

    const int nkv = bq + 1;
    for (int t = 0; t < nkv; ++t) {
        const int j0 = t * BK;
        __syncthreads();   // protect KsT/Vs/Rel/Ps from previous iteration's readers

        // ---- load K (transposed), V, Rel window ----
        const float* Kb = K + ((size_t)b * SEQ + j0) * DKK;
        const float* Vb = V + ((size_t)b * SEQ + j0) * DKK;
        #pragma unroll
        for (int idx = tid; idx < BK * DKK; idx += NT) {
            int j = idx >> 6, d = idx & 63;
            KsT[d * QS + j] = Kb[idx];
            Vs[idx] = Vb[idx];
        }
        const int cbase = SEQ - 64 - i0 + j0;   // >= 0 always
        #pragma unroll
        for (int idx = tid; idx < 64 * 128; idx += NT) {
            int d = idx >> 7, u = idx & 127;
            int c = cbase + u;
            Rel[d * 128 + u] = (c < SEQ) ? R[(size_t)d * SEQ + c] : 0.f;
        }
        __syncthreads();

        // ---- score tile: S[i,j] = Q[i]. (K[j] + Krel[:, shift]) ----
        float acc[16];
        #pragma unroll
        for (int x = 0; x < 16; ++x) acc[x] = 0.f;

        #pragma unroll 4
        for (int d = 0; d < DKK; ++d) {
            const float4 q4 = *(const float4*)(QsT + d * QS + ty * 4);
            const float4 k4 = *(const float4*)(KsT + d * QS + tx * 4);
            const float4 ra = *(const float4*)(Rel + d * 128 + relbase - 3);
            const float4 rc = *(const float4*)(Rel + d * 128 + relbase + 1);
            float qv[4] = {q4.x, q4.y, q4.z, q4.w};
            float kv[4] = {k4.x, k4.y, k4.z, k4.w};
            float rv[8] = {ra.x, ra.y, ra.z, ra.w, rc.x, rc.y, rc.z, rc.w};
            #pragma unroll
            for (int ii = 0; ii < 4; ++ii)
                #pragma unroll
                for (int jj = 0; jj < 4; ++jj)
                    acc[ii * 4 + jj] = fmaf(qv[ii], kv[jj] + rv[3 + jj - ii], acc[ii * 4 + jj]);
        }

        // ---- causal mask on diagonal tile ----
        if (j0 == i0) {
            #pragma unroll
            for (int ii = 0; ii < 4; ++ii)
                #pragma unroll
                for (int jj = 0; jj < 4; ++jj)
                    if (tx * 4 + jj > ty * 4 + ii) acc[ii * 4 + jj] = -INFINITY;
        }

        // ---- online softmax (rowwise over 16 lanes sharing ty) ----
        #pragma unroll
        for (int ii = 0; ii < 4; ++ii) {
            float mx = fmaxf(fmaxf(acc[ii*4], acc[ii*4+1]), fmaxf(acc[ii*4+2], acc[ii*4+3]));
            #pragma unroll
            for (int off = 8; off; off >>= 1)
                mx = fmaxf(mx, __shfl_xor_sync(0xffffffffu, mx, off, 16));
            const float mnew = fmaxf(m_i[ii], mx);
            const float corr = __expf(m_i[ii] - mnew);
            m_i[ii] = mnew;
            float ps = 0.f;
            #pragma unroll
            for (int jj = 0; jj < 4; ++jj) {
                float p = __expf(acc[ii*4+jj] - mnew);
                acc[ii*4+jj] = p;
                ps += p;
            }
            #pragma unroll
            for (int off = 8; off; off >>= 1)
                ps += __shfl_xor_sync(0xffffffffu, ps, off, 16);
            l_i[ii] = l_i[ii] * corr + ps;
            #pragma unroll
            for (int jj = 0; jj < 4; ++jj) accO[ii*4+jj] *= corr;
        }

        // ---- stage P to smem ----
        #pragma unroll
        for (int ii = 0; ii < 4; ++ii)
            *(float4*)(Ps + (ty * 4 + ii) * QS + tx * 4) =
                make_float4(acc[ii*4], acc[ii*4+1], acc[ii*4+2], acc[ii*4+3]);
        __syncthreads();

        // ---- O += P @ V ----
        #pragma unroll 2
        for (int j = 0; j < BK; j += 4) {
            float4 p4[4];
            #pragma unroll
            for (int ii = 0; ii < 4; ++ii)
                p4[ii] = *(const float4*)(Ps + (ty * 4 + ii) * QS + j);
            #pragma unroll
            for (int u = 0; u < 4; ++u) {
                const float4 v4 = *(const float4*)(Vs + (j + u) * 64 + tx * 4);
                #pragma unroll
                for (int ii = 0; ii < 4; ++ii) {
                    const float pv = ((const float*)&p4[ii])[u];
                    accO[ii*4+0] = fmaf(pv, v4.x, accO[ii*4+0]);
                    accO[ii*4+1] = fmaf(pv, v4.y, accO[ii*4+1]);
                    accO[ii*4+2] = fmaf(pv, v4.z, accO[ii*4+2]);
                    accO[ii*4+3] = fmaf(pv, v4.w, accO[ii*4+3]);
                }
            }
        }
    }

    // ---- epilogue: normalize + store ----
    float* Ob = O + ((size_t)b * SEQ + i0) * DKK;
    #pragma unroll
    for (int ii = 0; ii < 4; ++ii) {
        const float inv = 1.0f / l_i[ii];
        const int row = ty * 4 + ii;
        *(float4*)(Ob + row * DKK + tx * 4) =
            make_float4(accO[ii*4+0]*inv, accO[ii*4+1]*inv, accO[ii*4+2]*inv, accO[ii*4+3]*inv);
    }
}

extern "C" void kernel_launch(void* const* d_in, const int* in_sizes, int n_in,
                              void* d_out, int out_size)
{
    const float* Q = (const float*)d_in[0];
    const float* K = (const float*)d_in[1];
    const float* V = (const float*)d_in[2];
    const float* R = (const float*)d_in[3];   // Krelpos [64, 2048]
    float* O = (float*)d_out;

    cudaFuncSetAttribute(attn_relpos_kernel,
                         cudaFuncAttributeMaxDynamicSharedMemorySize, SMEM_BYTES);
    dim3 grid(SEQ / BQ, BSZ);   // 32 x 16
    attn_relpos_kernel<<<grid, NT, SMEM_BYTES>>>(Q, K, V, R, O);
}

// round 3
// speedup vs baseline: 1.0086x; 1.0086x over previous
#include <cuda_runtime.h>
#include <math.h>

#define BSZ 16
#define SEQ 2048
#define DKK 64
#define BQ 64
#define BK 64
#define NT 256
#define QS 68            // padded row stride for QsT/KsT/Ps (17*16B -> aligned float4, staggered banks)

// smem layout (floats):
//  QsT [64][68]  (d-major, transposed Q, pre-scaled by 1/8)
//  KsT [64][68]  (d-major, transposed K)
//  Vs  [64][64]  (j-major)
//  Rel [64][128] (d-major window of Krelpos columns)
//  Ps  [64][68]  (softmax probs, row-major)
#define SM_QST 0
#define SM_KST (SM_QST + 64*QS)
#define SM_VS  (SM_KST + 64*QS)
#define SM_REL (SM_VS  + 64*64)
#define SM_PS  (SM_REL + 64*128)
#define SM_FLOATS (SM_PS + 64*QS)
#define SMEM_BYTES (SM_FLOATS * 4)

__global__ __launch_bounds__(NT, 2)
void attn_relpos_kernel(const float* __restrict__ Q, const float* __restrict__ K,
                        const float* __restrict__ V, const float* __restrict__ R,
                        float* __restrict__ O)
{
    extern __shared__ float smem[];
    float* QsT = smem + SM_QST;
    float* KsT = smem + SM_KST;
    float* Vs  = smem + SM_VS;
    float* Rel = smem + SM_REL;
    float* Ps  = smem + SM_PS;

    const int tid = threadIdx.x;
    const int tx = tid & 15;      // col group (4 cols each)
    const int ty = tid >> 4;      // row group (4 rows each)

    // reversed tile order: heavy (long causal loop) CTAs launch first
    const int bq = (int)gridDim.x - 1 - (int)blockIdx.x;
    const int i0 = bq * BQ;
    const int b  = blockIdx.y;

    const float* Qb = Q + ((size_t)b * SEQ + i0) * DKK;

    // ---- load Q tile, transposed + pre-scaled by 1/sqrt(64) ----
    #pragma unroll
    for (int idx = tid; idx < BQ * DKK; idx += NT) {
        int i = idx >> 6, d = idx & 63;
        QsT[d * QS + i] = Qb[idx] * 0.125f;
    }

    float accO[16];
    #pragma unroll
    for (int x = 0; x < 16; ++x) accO[x] = 0.f;
    float m_i[4], l_i[4];
    #pragma unroll
    for (int x = 0; x < 4; ++x) { m_i[x] = -INFINITY; l_i[x] = 0.f; }

    const int relbase = 63 + 4 * (tx - ty);   // in [3,123]; relbase-3 is 16B aligned

    const int nkv = bq + 1;
    for (int t = 0; t < nkv; ++t) {
        const int j0 = t * BK;
        __syncthreads();   // protect KsT/Vs/Rel/Ps from previous iteration's readers

        // ---- load K (transposed), V, Rel window ----
        const float* Kb = K + ((size_t)b * SEQ + j0) * DKK;
        const float* Vb = V + ((size_t)b * SEQ + j0) * DKK;
        #pragma unroll
        for (int idx = tid; idx < BK * DKK; idx += NT) {
            int j = idx >> 6, d = idx & 63;
            KsT[d * QS + j] = Kb[idx];
            Vs[idx] = Vb[idx];
        }
        const int cbase = SEQ - 64 - i0 + j0;   // >= 0 always
        #pragma unroll
        for (int idx = tid; idx < 64 * 128; idx += NT) {
            int d = idx >> 7, u = idx & 127;
            int c = cbase + u;
            Rel[d * 128 + u] = (c < SEQ) ? R[(size_t)d * SEQ + c] : 0.f;
        }
        __syncthreads();

        // ---- score tile: S[i,j] = Q[i]. (K[j] + Krel[:, shift]) ----
        float acc[16];
        #pragma unroll
        for (int x = 0; x < 16; ++x) acc[x] = 0.f;

        #pragma unroll 4
        for (int d = 0; d < DKK; ++d) {
            const float4 q4 = *(const float4*)(QsT + d * QS + ty * 4);
            const float4 k4 = *(const float4*)(KsT + d * QS + tx * 4);
            const float4 ra = *(const float4*)(Rel + d * 128 + relbase - 3);
            const float4 rc = *(const float4*)(Rel + d * 128 + relbase + 1);
            float qv[4] = {q4.x, q4.y, q4.z, q4.w};
            float kv[4] = {k4.x, k4.y, k4.z, k4.w};
            float rv[8] = {ra.x, ra.y, ra.z, ra.w, rc.x, rc.y, rc.z, rc.w};
            #pragma unroll
            for (int ii = 0; ii < 4; ++ii)
                #pragma unroll
                for (int jj = 0; jj < 4; ++jj)
                    acc[ii * 4 + jj] = fmaf(qv[ii], kv[jj] + rv[3 + jj - ii], acc[ii * 4 + jj]);
        }

        // ---- causal mask on diagonal tile ----
        if (j0 == i0) {
            #pragma unroll
            for (int ii = 0; ii < 4; ++ii)
                #pragma unroll
                for (int jj = 0; jj < 4; ++jj)
                    if (tx * 4 + jj > ty * 4 + ii) acc[ii * 4 + jj] = -INFINITY;
        }

        // ---- online softmax (rowwise over 16 lanes sharing ty) ----
        #pragma unroll
        for (int ii = 0; ii < 4; ++ii) {
            float mx = fmaxf(fmaxf(acc[ii*4], acc[ii*4+1]), fmaxf(acc[ii*4+2], acc[ii*4+3]));
            #pragma unroll
            for (int off = 8; off; off >>= 1)
                mx = fmaxf(mx, __shfl_xor_sync(0xffffffffu, mx, off, 16));
            const float mnew = fmaxf(m_i[ii], mx);
            const float corr = __expf(m_i[ii] - mnew);
            m_i[ii] = mnew;
            float ps = 0.f;
            #pragma unroll
            for (int jj = 0; jj < 4; ++jj) {
                float p = __expf(acc[ii*4+jj] - mnew);
                acc[ii*4+jj] = p;
                ps += p;
            }
            #pragma unroll
            for (int off = 8; off; off >>= 1)
                ps += __shfl_xor_sync(0xffffffffu, ps, off, 16);
            l_i[ii] = l_i[ii] * corr + ps;
            #pragma unroll
            for (int jj = 0; jj < 4; ++jj) accO[ii*4+jj] *= corr;
        }

        // ---- stage P to smem ----
        #pragma unroll
        for (int ii = 0; ii < 4; ++ii)
            *(float4*)(Ps + (ty * 4 + ii) * QS + tx * 4) =
                make_float4(acc[ii*4], acc[ii*4+1], acc[ii*4+2], acc[ii*4+3]);
        __syncthreads();

        // ---- O += P @ V ----
        #pragma unroll 2
        for (int j = 0; j < BK; j += 4) {
            float4 p4[4];
            #pragma unroll
            for (int ii = 0; ii < 4; ++ii)
                p4[ii] = *(const float4*)(Ps + (ty * 4 + ii) * QS + j);
            #pragma unroll
            for (int u = 0; u < 4; ++u) {
                const float4 v4 = *(const float4*)(Vs + (j + u) * 64 + tx * 4);
                #pragma unroll
                for (int ii = 0; ii < 4; ++ii) {
                    const float pv = ((const float*)&p4[ii])[u];
                    accO[ii*4+0] = fmaf(pv, v4.x, accO[ii*4+0]);
                    accO[ii*4+1] = fmaf(pv, v4.y, accO[ii*4+1]);
                    accO[ii*4+2] = fmaf(pv, v4.z, accO[ii*4+2]);
                    accO[ii*4+3] = fmaf(pv, v4.w, accO[ii*4+3]);
                }
            }
        }
    }

    // ---- epilogue: normalize + store ----
    float* Ob = O + ((size_t)b * SEQ + i0) * DKK;
    #pragma unroll
    for (int ii = 0; ii < 4; ++ii) {
        const float inv = 1.0f / l_i[ii];
        const int row = ty * 4 + ii;
        *(float4*)(Ob + row * DKK + tx * 4) =
            make_float4(accO[ii*4+0]*inv, accO[ii*4+1]*inv, accO[ii*4+2]*inv, accO[ii*4+3]*inv);
    }
}

extern "C" void kernel_launch(void* const* d_in, const int* in_sizes, int n_in,
                              void* d_out, int out_size)
{
    const float* Q = (const float*)d_in[0];
    const float* K = (const float*)d_in[1];
    const float* V = (const float*)d_in[2];
    const float* R = (const float*)d_in[3];   // Krelpos [64, 2048]
    float* O = (float*)d_out;

    cudaFuncSetAttribute(attn_relpos_kernel,
                         cudaFuncAttributeMaxDynamicSharedMemorySize, SMEM_BYTES);
    dim3 grid(SEQ / BQ, BSZ);   // 32 x 16
    attn_relpos_kernel<<<grid, NT, SMEM_BYTES>>>(Q, K, V, R, O);
}

// round 4
// speedup vs baseline: 2.4193x; 2.3987x over previous
#include <cuda_runtime.h>
#include <cuda_bf16.h>
#include <math.h>
#include <stdint.h>

#define BSZ 16
#define SEQ 2048
#define BQ  128
#define BK  64
#define NT  256
#define ST  72     // row stride (elems) Q/K/V tiles
#define RST 200    // row stride (elems) R window tile (192 data cols)
#define QWST 88    // row stride (floats) per-warp QW scatter buffer

typedef __nv_bfloat16 bf16;

// ---- smem byte offsets ----
#define OFF_QW 0                           // 8 warps * 16 * 88 * 4 = 45056
#define OFF_QH (OFF_QW + 8*16*QWST*4)
#define OFF_QL (OFF_QH + BQ*ST*2)          // 18432 each
#define OFF_KH (OFF_QL + BQ*ST*2)
#define OFF_KL (OFF_KH + BK*ST*2)          // 9216 each
#define OFF_VH (OFF_KL + BK*ST*2)
#define OFF_VL (OFF_VH + BK*ST*2)
#define OFF_RH (OFF_VL + BK*ST*2)
#define SMEM_BYTES (OFF_RH + 64*RST*2)     // total = 144384
static_assert(SMEM_BYTES <= 227*1024, "smem");

__device__ __forceinline__ uint32_t pk(__nv_bfloat16 a, __nv_bfloat16 b) {
    return (uint32_t)__bfloat16_as_ushort(a) | ((uint32_t)__bfloat16_as_ushort(b) << 16);
}
__device__ __forceinline__ void split4(float4 f, uint2 &h, uint2 &l) {
    __nv_bfloat16 hx=__float2bfloat16_rn(f.x), hy=__float2bfloat16_rn(f.y),
                  hz=__float2bfloat16_rn(f.z), hw=__float2bfloat16_rn(f.w);
    __nv_bfloat16 lx=__float2bfloat16_rn(f.x-__bfloat162float(hx)),
                  ly=__float2bfloat16_rn(f.y-__bfloat162float(hy)),
                  lz=__float2bfloat16_rn(f.z-__bfloat162float(hz)),
                  lw=__float2bfloat16_rn(f.w-__bfloat162float(hw));
    h.x=pk(hx,hy); h.y=pk(hz,hw); l.x=pk(lx,ly); l.y=pk(lz,lw);
}
__device__ __forceinline__ void ldmx4(uint32_t r[4], const void* p) {
    uint32_t a = (uint32_t)__cvta_generic_to_shared(p);
    asm volatile("ldmatrix.sync.aligned.m8n8.x4.shared.b16 {%0,%1,%2,%3}, [%4];\n"
                 : "=r"(r[0]),"=r"(r[1]),"=r"(r[2]),"=r"(r[3]) : "r"(a));
}
__device__ __forceinline__ void ldmx4t(uint32_t r[4], const void* p) {
    uint32_t a = (uint32_t)__cvta_generic_to_shared(p);
    asm volatile("ldmatrix.sync.aligned.m8n8.x4.trans.shared.b16 {%0,%1,%2,%3}, [%4];\n"
                 : "=r"(r[0]),"=r"(r[1]),"=r"(r[2]),"=r"(r[3]) : "r"(a));
}
__device__ __forceinline__ void mma(float c[4], const uint32_t a[4], uint32_t b0, uint32_t b1) {
    asm volatile("mma.sync.aligned.m16n8k16.row.col.f32.bf16.bf16.f32 "
                 "{%0,%1,%2,%3},{%4,%5,%6,%7},{%8,%9},{%0,%1,%2,%3};\n"
                 : "+f"(c[0]),"+f"(c[1]),"+f"(c[2]),"+f"(c[3])
                 : "r"(a[0]),"r"(a[1]),"r"(a[2]),"r"(a[3]),"r"(b0),"r"(b1));
}

__global__ __launch_bounds__(NT, 1)
void attn_relpos_mma(const float* __restrict__ Q, const float* __restrict__ K,
                     const float* __restrict__ V, const float* __restrict__ R,
                     float* __restrict__ O)
{
    extern __shared__ char smc[];
    float* QW = (float*)(smc + OFF_QW);
    bf16* Qh = (bf16*)(smc + OFF_QH);
    bf16* Ql = (bf16*)(smc + OFF_QL);
    bf16* Kh = (bf16*)(smc + OFF_KH);
    bf16* Kl = (bf16*)(smc + OFF_KL);
    bf16* Vh = (bf16*)(smc + OFF_VH);
    bf16* Vl = (bf16*)(smc + OFF_VL);
    bf16* Rh = (bf16*)(smc + OFF_RH);

    const int tid  = threadIdx.x;
    const int w    = tid >> 5;
    const int lane = tid & 31;
    const int g    = lane >> 2;    // row group 0..7
    const int tq   = lane & 3;     // col thread 0..3

    const int bq = (int)gridDim.x - 1 - (int)blockIdx.x;   // heavy CTAs first
    const int i0 = bq * BQ;
    const int b  = blockIdx.y;
    const int iw = i0 + w * 16;

    const float* Qb = Q + ((size_t)b * SEQ + i0) * 64;

    // ---- stage Q tile (prescaled by 1/8), hi/lo split ----
    #pragma unroll
    for (int r = 0; r < 8; ++r) {
        int idx = tid + r * NT;               // float4 index 0..2047
        int i = idx >> 4, d4 = (idx & 15) << 2;
        float4 f = *(const float4*)(Qb + i * 64 + d4);
        f.x *= 0.125f; f.y *= 0.125f; f.z *= 0.125f; f.w *= 0.125f;
        uint2 h, l; split4(f, h, l);
        *(uint2*)(Qh + i * ST + d4) = h;
        *(uint2*)(Ql + i * ST + d4) = l;
    }
    __syncthreads();

    // ---- preload Q A-fragments (held across whole loop) ----
    uint32_t qa_h[4][4], qa_l[4][4];
    {
        const int ar = w * 16 + (lane & 15);
        const int ac = (lane >> 4) << 3;
        #pragma unroll
        for (int kc = 0; kc < 4; ++kc) {
            ldmx4(qa_h[kc], Qh + ar * ST + kc * 16 + ac);
            ldmx4(qa_l[kc], Ql + ar * ST + kc * 16 + ac);
        }
    }

    float accO[8][4];
    #pragma unroll
    for (int nb = 0; nb < 8; ++nb)
        #pragma unroll
        for (int x = 0; x < 4; ++x) accO[nb][x] = 0.f;
    float m0 = -INFINITY, m1 = -INFINITY, l0 = 0.f, l1 = 0.f;

    float* QWw = QW + w * 16 * QWST;
    const int nkv = 2 * bq + 2;

    for (int t = 0; t < nkv; ++t) {
        const int j0 = t * BK;
        __syncthreads();

        // ---- stage K, V (hi/lo) ----
        const float* Kb = K + ((size_t)b * SEQ + j0) * 64;
        const float* Vb = V + ((size_t)b * SEQ + j0) * 64;
        #pragma unroll
        for (int r = 0; r < 4; ++r) {
            int idx = tid + r * NT;           // float4 index 0..1023
            int j = idx >> 4, d4 = (idx & 15) << 2;
            uint2 h, l;
            float4 fk = *(const float4*)(Kb + j * 64 + d4);
            split4(fk, h, l);
            *(uint2*)(Kh + j * ST + d4) = h;
            *(uint2*)(Kl + j * ST + d4) = l;
            float4 fv = *(const float4*)(Vb + j * 64 + d4);
            split4(fv, h, l);
            *(uint2*)(Vh + j * ST + d4) = h;
            *(uint2*)(Vl + j * ST + d4) = l;
        }
        // ---- stage R window (hi only): Rh[d][v], v = c - cwin0 ----
        const int cwin0 = SEQ - 128 - i0 + j0;
        #pragma unroll
        for (int r = 0; r < 12; ++r) {
            int idx = tid + r * NT;           // float4 index 0..3071
            int d = idx / 48, v4 = (idx % 48) << 2;
            int c = cwin0 + v4;
            float4 f = make_float4(0.f, 0.f, 0.f, 0.f);
            if (c < SEQ) f = *(const float4*)(R + (size_t)d * SEQ + c);
            uint2 h;
            h.x = pk(__float2bfloat16_rn(f.x), __float2bfloat16_rn(f.y));
            h.y = pk(__float2bfloat16_rn(f.z), __float2bfloat16_rn(f.w));
            *(uint2*)(Rh + d * RST + v4) = h;
        }
        __syncthreads();

        if (j0 <= iw + 15) {   // warp has at least one unmasked row
            // ---- bias GEMM: QW[il][u] = Q(rows) . R(window cols), hi-pass ----
            const int v0w = 112 - 16 * w;
            const int trow = ((lane >> 4) << 3) + (lane & 7);   // trans k-row part
            const int tcol = ((lane >> 3) & 1) << 3;            // trans n-col part
            #pragma unroll
            for (int np = 0; np < 5; ++np) {
                float cw0[4] = {0.f,0.f,0.f,0.f}, cw1[4] = {0.f,0.f,0.f,0.f};
                #pragma unroll
                for (int kc = 0; kc < 4; ++kc) {
                    uint32_t rb[4];
                    ldmx4t(rb, Rh + (kc * 16 + trow) * RST + v0w + np * 16 + tcol);
                    mma(cw0, qa_h[kc], rb[0], rb[2]);
                    mma(cw1, qa_h[kc], rb[1], rb[3]);
                }
                const int uc = np * 16 + 2 * tq;
                *(float2*)(QWw + g * QWST + uc)           = make_float2(cw0[0], cw0[1]);
                *(float2*)(QWw + (g + 8) * QWST + uc)     = make_float2(cw0[2], cw0[3]);
                *(float2*)(QWw + g * QWST + uc + 8)       = make_float2(cw1[0], cw1[1]);
                *(float2*)(QWw + (g + 8) * QWST + uc + 8) = make_float2(cw1[2], cw1[3]);
            }
            __syncwarp();

            // ---- S GEMM (3-pass) ----
            float sc[8][4];
            #pragma unroll
            for (int nb = 0; nb < 8; ++nb)
                #pragma unroll
                for (int x = 0; x < 4; ++x) sc[nb][x] = 0.f;
            {
                const int br = lane & 15;
                const int bc = (lane >> 4) << 3;
                #pragma unroll
                for (int np = 0; np < 4; ++np) {
                    #pragma unroll
                    for (int kc = 0; kc < 4; ++kc) {
                        uint32_t kh[4], kl[4];
                        ldmx4(kh, Kh + (np * 16 + br) * ST + kc * 16 + bc);
                        ldmx4(kl, Kl + (np * 16 + br) * ST + kc * 16 + bc);
                        mma(sc[2*np],   qa_h[kc], kh[0], kh[2]);
                        mma(sc[2*np+1], qa_h[kc], kh[1], kh[3]);
                        mma(sc[2*np],   qa_h[kc], kl[0], kl[2]);
                        mma(sc[2*np+1], qa_h[kc], kl[1], kl[3]);
                        mma(sc[2*np],   qa_l[kc], kh[0], kh[2]);
                        mma(sc[2*np+1], qa_l[kc], kh[1], kh[3]);
                    }
                }
            }

            // ---- add skewed bias from QW buffer ----
            #pragma unroll
            for (int nb = 0; nb < 8; ++nb) {
                int u0 = 8 * nb + 2 * tq + 15 - g;   // row g
                int u1 = 8 * nb + 2 * tq + 7 - g;    // row g+8
                sc[nb][0] += QWw[g * QWST + u0];
                sc[nb][1] += QWw[g * QWST + u0 + 1];
                sc[nb][2] += QWw[(g + 8) * QWST + u1];
                sc[nb][3] += QWw[(g + 8) * QWST + u1 + 1];
            }

            // ---- causal mask ----
            if (j0 + 63 > iw) {
                const int ia = iw + g, ib = iw + 8 + g;
                #pragma unroll
                for (int nb = 0; nb < 8; ++nb) {
                    int j = j0 + 8 * nb + 2 * tq;
                    if (j     > ia) sc[nb][0] = -INFINITY;
                    if (j + 1 > ia) sc[nb][1] = -INFINITY;
                    if (j     > ib) sc[nb][2] = -INFINITY;
                    if (j + 1 > ib) sc[nb][3] = -INFINITY;
                }
            }

            // ---- online softmax (rows g / g+8) ----
            float mx0 = -INFINITY, mx1 = -INFINITY;
            #pragma unroll
            for (int nb = 0; nb < 8; ++nb) {
                mx0 = fmaxf(mx0, fmaxf(sc[nb][0], sc[nb][1]));
                mx1 = fmaxf(mx1, fmaxf(sc[nb][2], sc[nb][3]));
            }
            mx0 = fmaxf(mx0, __shfl_xor_sync(0xffffffffu, mx0, 1));
            mx0 = fmaxf(mx0, __shfl_xor_sync(0xffffffffu, mx0, 2));
            mx1 = fmaxf(mx1, __shfl_xor_sync(0xffffffffu, mx1, 1));
            mx1 = fmaxf(mx1, __shfl_xor_sync(0xffffffffu, mx1, 2));
            const float mn0 = fmaxf(m0, mx0), mn1 = fmaxf(m1, mx1);
            const float cor0 = __expf(m0 - mn0), cor1 = __expf(m1 - mn1);
            m0 = mn0; m1 = mn1;
            float ps0 = 0.f, ps1 = 0.f;
            #pragma unroll
            for (int nb = 0; nb < 8; ++nb) {
                sc[nb][0] = __expf(sc[nb][0] - mn0); ps0 += sc[nb][0];
                sc[nb][1] = __expf(sc[nb][1] - mn0); ps0 += sc[nb][1];
                sc[nb][2] = __expf(sc[nb][2] - mn1); ps1 += sc[nb][2];
                sc[nb][3] = __expf(sc[nb][3] - mn1); ps1 += sc[nb][3];
            }
            ps0 += __shfl_xor_sync(0xffffffffu, ps0, 1);
            ps0 += __shfl_xor_sync(0xffffffffu, ps0, 2);
            ps1 += __shfl_xor_sync(0xffffffffu, ps1, 1);
            ps1 += __shfl_xor_sync(0xffffffffu, ps1, 2);
            l0 = l0 * cor0 + ps0;
            l1 = l1 * cor1 + ps1;
            #pragma unroll
            for (int nb = 0; nb < 8; ++nb) {
                accO[nb][0] *= cor0; accO[nb][1] *= cor0;
                accO[nb][2] *= cor1; accO[nb][3] *= cor1;
            }

            // ---- PV GEMM (3-pass), P register-direct ----
            #pragma unroll
            for (int kc = 0; kc < 4; ++kc) {
                uint32_t pah[4], pal[4];
                #pragma unroll
                for (int q = 0; q < 4; ++q) {
                    const int nb = 2 * kc + (q >> 1);
                    const int r0 = (q & 1) ? 2 : 0;
                    float p0 = sc[nb][r0], p1 = sc[nb][r0 + 1];
                    __nv_bfloat16 h0 = __float2bfloat16_rn(p0), h1 = __float2bfloat16_rn(p1);
                    pah[(q >> 1) * 2 + (q & 1)] = pk(h0, h1);
                    pal[(q >> 1) * 2 + (q & 1)] =
                        pk(__float2bfloat16_rn(p0 - __bfloat162float(h0)),
                           __float2bfloat16_rn(p1 - __bfloat162float(h1)));
                }
                #pragma unroll
                for (int np = 0; np < 4; ++np) {
                    uint32_t vh[4], vl[4];
                    ldmx4t(vh, Vh + (kc * 16 + trow) * ST + np * 16 + tcol);
                    ldmx4t(vl, Vl + (kc * 16 + trow) * ST + np * 16 + tcol);
                    mma(accO[2*np],   pah, vh[0], vh[2]);
                    mma(accO[2*np+1], pah, vh[1], vh[3]);
                    mma(accO[2*np],   pal, vh[0], vh[2]);
                    mma(accO[2*np+1], pal, vh[1], vh[3]);
                    mma(accO[2*np],   pah, vl[0], vl[2]);
                    mma(accO[2*np+1], pah, vl[1], vl[3]);
                }
            }
        }
    }

    // ---- epilogue ----
    const float inv0 = 1.0f / l0, inv1 = 1.0f / l1;
    float* Ob = O + ((size_t)b * SEQ + iw) * 64;
    #pragma unroll
    for (int nb = 0; nb < 8; ++nb) {
        const int dc = 8 * nb + 2 * tq;
        *(float2*)(Ob + g * 64 + dc)       = make_float2(accO[nb][0] * inv0, accO[nb][1] * inv0);
        *(float2*)(Ob + (g + 8) * 64 + dc) = make_float2(accO[nb][2] * inv1, accO[nb][3] * inv1);
    }
}

extern "C" void kernel_launch(void* const* d_in, const int* in_sizes, int n_in,
                              void* d_out, int out_size)
{
    const float* Q = (const float*)d_in[0];
    const float* K = (const float*)d_in[1];
    const float* V = (const float*)d_in[2];
    const float* R = (const float*)d_in[3];
    float* O = (float*)d_out;

    cudaFuncSetAttribute(attn_relpos_mma,
                         cudaFuncAttributeMaxDynamicSharedMemorySize, SMEM_BYTES);
    dim3 grid(SEQ / BQ, BSZ);   // 16 x 16
    attn_relpos_mma<<<grid, NT, SMEM_BYTES>>>(Q, K, V, R, O);
}